// round 9
// baseline (speedup 1.0000x reference)
#include <cuda_runtime.h>
#include <math_constants.h>

// Problem constants (from reference setup_inputs)
constexpr int B = 32;
constexpr int F = 1024;
constexpr int S = 2048;
constexpr int K = 16;

constexpr int NBLK = 1024;                 // total blocks
constexpr int RG = 16;                     // row groups per batch (128 rows each)
constexpr int ROWS_PER_RG = S / RG;        // 128
constexpr int COLS_PER_CG = 32;            // cols per block
constexpr int CG = S / COLS_PER_CG;        // 64 col groups

// Scratch (no allocations allowed anywhere). All counters/flags self-reset.
__device__ float g_partial[(size_t)B * RG * S];   // 4 MiB
__device__ int   g_idx[B * K];
__device__ int   g_done[B];                       // stage-arrival counters
__device__ int   g_ready[B];                      // topk-published flags
__device__ int   g_done2[B];                      // gather-arrival counters

// Gather one f-row (beta) of batch g: 16 scattered loads + 64B store.
__device__ __forceinline__ void gather_row(int g, int beta, int t,
                                           const float* __restrict__ x,
                                           float* __restrict__ out) {
    if (t == 0) {
        while (atomicAdd(&g_ready[g], 0) == 0) __nanosleep(100);
    }
    __syncthreads();
    __threadfence();
    if (t < K) {
        int s = g_idx[g * K + t];
        out[((size_t)g * F + beta) * K + t] = __ldg(&x[((size_t)g * F + beta) * S + s]);
    }
    __syncthreads();
    if (t == 0) {
        int o2 = atomicAdd(&g_done2[g], 1);
        if (o2 == NBLK - 1) { g_ready[g] = 0; g_done2[g] = 0; }  // replay reset
    }
}

// ---------------------------------------------------------------------------
// Fused, batch-staged kernel. Each block loops over all 32 batches; at stage
// b the full grid collectively streams w[b], so batches complete in a
// staggered fashion and their top-k + gather overlap the remaining stream.
// First-arrival election rotates the top-k duty (self-balancing: the elected
// block burns its lead spinning, then falls behind).
// Deterministic: fixed accumulation order everywhere, no float atomics.
// Tie-break: smaller index wins; indices emitted in descending-value order
// (matches lax.top_k; the gather output ordering depends on it).
// Whole grid co-resident (256 thr, 8 blk/SM -> 1184 slots >= 1024 blocks;
// 2048 thr/SM; ~12.6KB smem * 8 ~ 101KB < 228KB), so spins cannot deadlock.
// ---------------------------------------------------------------------------
__global__ __launch_bounds__(256, 8) void fused_kernel(const float* __restrict__ w,
                                                       const float* __restrict__ x,
                                                       float* __restrict__ out) {
    int beta = blockIdx.x;
    int rg = beta >> 6;                 // 0..15 row group
    int cg = beta & (CG - 1);           // 0..63 col group
    int t  = threadIdx.x;
    int q  = t & 7;                     // col quad within the 32 cols
    int rr = t >> 3;                    // 0..31

    __shared__ float s_red[32][33];     // [col][rr], padded
    __shared__ float vals[S];           // 8 KB topk scratch
    __shared__ float wv[8];
    __shared__ int   wi[8];
    __shared__ int   s_flag;

    for (int b = 0; b < B; ++b) {
        // ---- stage b: stream this block's 128x32 tile of w[b] (evict-first:
        //      w is read exactly once; keep L2 for partials + x) ----
        const float4* __restrict__ base4 = reinterpret_cast<const float4*>(
            w + ((size_t)b * S + rg * ROWS_PER_RG) * S + cg * COLS_PER_CG);
        float4 a = make_float4(0.f, 0.f, 0.f, 0.f);
        #pragma unroll
        for (int i = 0; i < 4; ++i) {
            float4 v = __ldcs(&base4[(size_t)(rr + 32 * i) * (S / 4) + q]);
            a.x += v.x; a.y += v.y; a.z += v.z; a.w += v.w;
        }
        __syncthreads();                               // smem reuse guard
        s_red[q * 4 + 0][rr] = a.x;
        s_red[q * 4 + 1][rr] = a.y;
        s_red[q * 4 + 2][rr] = a.z;
        s_red[q * 4 + 3][rr] = a.w;
        __syncthreads();
        if (t < 32) {
            float sum = 0.f;
            #pragma unroll
            for (int j = 0; j < 32; ++j) sum += s_red[t][j];
            g_partial[((size_t)b * RG + rg) * S + cg * COLS_PER_CG + t] = sum;
        }
        __syncthreads();
        if (t == 0) {
            __threadfence();                           // publish partial
            int old = atomicAdd(&g_done[b], 1);
            s_flag = (old == 0);                       // first-arrival election
        }
        __syncthreads();

        if (s_flag) {
            // ---- elected: wait for all partials, reduce, top-16 ----
            if (t == 0) {
                while (atomicAdd(&g_done[b], 0) < NBLK) __nanosleep(100);
            }
            __syncthreads();
            __threadfence();                           // acquire partials

            for (int s = t; s < S; s += 256) {
                float acc = 0.f;
                #pragma unroll
                for (int r = 0; r < RG; ++r)
                    acc += g_partial[((size_t)b * RG + r) * S + s];
                vals[s] = acc;
            }
            __syncthreads();

            int lane = t & 31, warp = t >> 5;
            for (int k = 0; k < K; ++k) {
                float best = -CUDART_INF_F;
                int bi = S;
                #pragma unroll
                for (int j = 0; j < S / 256; ++j) {
                    int s = t + j * 256;
                    float v = vals[s];
                    if (v > best || (v == best && s < bi)) { best = v; bi = s; }
                }
                #pragma unroll
                for (int off = 16; off > 0; off >>= 1) {
                    float ov = __shfl_xor_sync(0xFFFFFFFFu, best, off);
                    int   oi = __shfl_xor_sync(0xFFFFFFFFu, bi,   off);
                    if (ov > best || (ov == best && oi < bi)) { best = ov; bi = oi; }
                }
                if (lane == 0) { wv[warp] = best; wi[warp] = bi; }
                __syncthreads();
                if (t == 0) {
                    float bb = wv[0]; int ii = wi[0];
                    #pragma unroll
                    for (int wdx = 1; wdx < 8; ++wdx) {
                        if (wv[wdx] > bb || (wv[wdx] == bb && wi[wdx] < ii)) {
                            bb = wv[wdx]; ii = wi[wdx];
                        }
                    }
                    g_idx[b * K + k] = ii;
                    vals[ii] = -CUDART_INF_F;          // knockout
                }
                __syncthreads();
            }
            if (t == 0) {
                g_done[b] = 0;                          // replay reset (count full)
                __threadfence();                        // publish g_idx
                atomicExch(&g_ready[b], 1);
            }
        }

        // ---- overlapped gather, 2 stages behind the stream ----
        if (b >= 2) gather_row(b - 2, beta, t, x, out);
    }

    // ---- tail gathers for the last two batches ----
    gather_row(B - 2, beta, t, x, out);
    gather_row(B - 1, beta, t, x, out);
}

extern "C" void kernel_launch(void* const* d_in, const int* in_sizes, int n_in,
                              void* d_out, int out_size) {
    const float* x = (const float*)d_in[0];   // [B, F, S]
    const float* w = (const float*)d_in[1];   // [B, S, S]
    float* out = (float*)d_out;               // [B, F, K]

    fused_kernel<<<NBLK, 256>>>(w, x, out);
}

// round 11
// speedup vs baseline: 2.7315x; 2.7315x over previous
#include <cuda_runtime.h>
#include <math_constants.h>

// Problem constants (from reference setup_inputs)
constexpr int B = 32;
constexpr int F = 1024;
constexpr int S = 2048;
constexpr int K = 16;

constexpr int NBLK = 1024;                  // grid size (co-resident: 8/SM * 148)
constexpr int TILE_ROWS = 512;              // rows per tile
constexpr int TILE_COLS = 32;               // cols per tile
constexpr int RGRP = S / TILE_ROWS;         // 4 row groups per batch
constexpr int CGRP = S / TILE_COLS;         // 64 col groups per batch
constexpr int TILES_PER_B = RGRP * CGRP;    // 256
constexpr int NTILES = B * TILES_PER_B;     // 8192
constexpr int ROUNDS = NTILES / NBLK;       // 8 tiles per block
constexpr int COHORT = 8;                   // gather blocks per batch
constexpr int FCHUNK = F / COHORT;          // 128 f-rows per gather chunk

// Scratch (no allocations anywhere). All counters/flags self-reset per run.
__device__ float g_part[B * RGRP * S];      // 1 MiB: per-(b,rg) column sums
__device__ int   g_idx[B * K];
__device__ int   g_done[B];                 // tile-arrival counters (0..256)
__device__ int   g_ready[B];                // topk-published flags
__device__ int   g_cd[B];                   // cohort-gather completion counters

// ---------------------------------------------------------------------------
// Single fused kernel, static batch-major tile schedule.
//   - Block i streams tiles {i, i+1024, ...}: tiles ordered batch-major, so
//     batches complete streaming staggered (~4-batch window in flight).
//   - Each tile: 512x32 chunk of w[b]; 16 unrolled LDG.128/thread (deep MLP),
//     in-block smem reduce -> 32 final column sums. Deterministic order.
//   - Arrival #255 for batch b: reduce 4 partials/col + iterative warp-shuffle
//     top-16 (tie-break: smaller index; emitted in descending-value order,
//     matching lax.top_k). Publishes g_idx, raises ready[b].
//   - Arrivals #247..254: gather cohort. Brief volatile-poll on ready[b]
//     (waiting only on the already-running elected block -> no deadlock),
//     then each gathers 128 f-rows of out[b]. Overlaps remaining streaming.
//   - No queue atomics; per-tile one atomicAdd to one of 32 addresses.
// ---------------------------------------------------------------------------
__global__ __launch_bounds__(256, 8) void fused_kernel(const float* __restrict__ w,
                                                       const float* __restrict__ x,
                                                       float* __restrict__ out) {
    const int t  = threadIdx.x;
    const int q  = t & 7;                   // float4 column within 32 cols
    const int rr = t >> 3;                  // 0..31 row phase

    __shared__ float s_red[32][33];         // [col][rr], padded
    __shared__ float vals[S];               // 8 KB (elected top-k only)
    __shared__ float wv[8];
    __shared__ int   wi[8];
    __shared__ int   s_old;
    __shared__ int   s_sidx[K];

    for (int r = 0; r < ROUNDS; ++r) {
        const int T  = r * NBLK + blockIdx.x;      // batch-major tile id
        const int b  = T >> 8;                     // / TILES_PER_B
        const int u  = T & (TILES_PER_B - 1);
        const int rg = u >> 6;                     // 0..3
        const int cc = u & (CGRP - 1);             // 0..63

        // ---- stream 512x32 tile of w[b]; evict-first (read-once data) ----
        const float4* __restrict__ base4 = reinterpret_cast<const float4*>(
            w + ((size_t)b * S + (size_t)rg * TILE_ROWS) * S + cc * TILE_COLS);
        float4 a = make_float4(0.f, 0.f, 0.f, 0.f);
        #pragma unroll 8
        for (int i = 0; i < TILE_ROWS / 32; ++i) {       // 16 iters
            float4 v = __ldcs(&base4[(size_t)(rr + 32 * i) * (S / 4) + q]);
            a.x += v.x; a.y += v.y; a.z += v.z; a.w += v.w;
        }
        __syncthreads();                                  // s_red reuse guard
        s_red[q * 4 + 0][rr] = a.x;
        s_red[q * 4 + 1][rr] = a.y;
        s_red[q * 4 + 2][rr] = a.z;
        s_red[q * 4 + 3][rr] = a.w;
        __syncthreads();
        if (t < 32) {
            float sum = 0.f;
            #pragma unroll
            for (int j = 0; j < 32; ++j) sum += s_red[t][j];
            g_part[((size_t)b * RGRP + rg) * S + cc * TILE_COLS + t] = sum;
        }
        __syncthreads();
        if (t == 0) {
            __threadfence();                              // publish partial
            s_old = atomicAdd(&g_done[b], 1);
        }
        __syncthreads();
        const int old = s_old;

        if (old == TILES_PER_B - 1) {
            // ---- elected: all partials in; reduce + top-16 ----
            __threadfence();                              // acquire partials
            for (int s = t; s < S; s += 256) {
                float acc = 0.f;
                #pragma unroll
                for (int g = 0; g < RGRP; ++g)
                    acc += g_part[((size_t)b * RGRP + g) * S + s];
                vals[s] = acc;
            }
            __syncthreads();

            const int lane = t & 31, warp = t >> 5;
            for (int k = 0; k < K; ++k) {
                float best = -CUDART_INF_F;
                int bi = S;
                #pragma unroll
                for (int j = 0; j < S / 256; ++j) {
                    int s = t + j * 256;
                    float v = vals[s];
                    if (v > best || (v == best && s < bi)) { best = v; bi = s; }
                }
                #pragma unroll
                for (int off = 16; off > 0; off >>= 1) {
                    float ov = __shfl_xor_sync(0xFFFFFFFFu, best, off);
                    int   oi = __shfl_xor_sync(0xFFFFFFFFu, bi,   off);
                    if (ov > best || (ov == best && oi < bi)) { best = ov; bi = oi; }
                }
                if (lane == 0) { wv[warp] = best; wi[warp] = bi; }
                __syncthreads();
                if (t == 0) {
                    float bb = wv[0]; int ii = wi[0];
                    #pragma unroll
                    for (int wdx = 1; wdx < 8; ++wdx) {
                        if (wv[wdx] > bb || (wv[wdx] == bb && wi[wdx] < ii)) {
                            bb = wv[wdx]; ii = wi[wdx];
                        }
                    }
                    g_idx[b * K + k] = ii;
                    vals[ii] = -CUDART_INF_F;             // knockout
                }
                __syncthreads();
            }
            if (t == 0) {
                g_done[b] = 0;                            // replay reset
                __threadfence();                          // publish g_idx
                atomicExch(&g_ready[b], 1);
            }
        } else if (old >= TILES_PER_B - 1 - COHORT) {
            // ---- gather cohort: chunk = old - 247 in [0,7] ----
            const int chunk = old - (TILES_PER_B - 1 - COHORT);
            if (t == 0) {
                while (((volatile int*)g_ready)[b] == 0) __nanosleep(100);
            }
            __syncthreads();
            __threadfence();                              // acquire g_idx
            if (t < K) s_sidx[t] = g_idx[b * K + t];
            __syncthreads();

            const int k  = t & 15;
            const int f0 = chunk * FCHUNK + (t >> 4);     // 16 f-rows per pass
            const int sc = s_sidx[k];
            #pragma unroll
            for (int j = 0; j < FCHUNK / 16; ++j) {       // 8 passes
                int f = f0 + 16 * j;
                out[((size_t)b * F + f) * K + k] =
                    __ldg(&x[((size_t)b * F + f) * S + sc]);
            }
            __syncthreads();
            if (t == 0) {
                int o2 = atomicAdd(&g_cd[b], 1);
                if (o2 == COHORT - 1) { g_ready[b] = 0; g_cd[b] = 0; }  // reset
            }
        }
    }
}

extern "C" void kernel_launch(void* const* d_in, const int* in_sizes, int n_in,
                              void* d_out, int out_size) {
    const float* x = (const float*)d_in[0];   // [B, F, S]
    const float* w = (const float*)d_in[1];   // [B, S, S]
    float* out = (float*)d_out;               // [B, F, K]

    fused_kernel<<<NBLK, 256>>>(w, x, out);
}

// round 12
// speedup vs baseline: 4.2171x; 1.5439x over previous
#include <cuda_runtime.h>
#include <math_constants.h>

// Problem constants (from reference setup_inputs)
constexpr int B = 32;
constexpr int F = 1024;
constexpr int S = 2048;
constexpr int K = 16;

constexpr int NBLK = 1024;                  // grid (co-resident: 8/SM * 148 = 1184)
constexpr int TILE_ROWS = 512;
constexpr int TILE_COLS = 32;
constexpr int RGRP = S / TILE_ROWS;         // 4
constexpr int CGRP = S / TILE_COLS;         // 64
constexpr int TILES_PER_B = RGRP * CGRP;    // 256
constexpr int GC = 32;                      // gather chunks per batch (32 f-rows each)
constexpr int PERIOD = TILES_PER_B + GC;    // 288
constexpr int TOTAL_W = B * PERIOD + 2 * GC;// 9280 (batches 30,31 gathers appended)

// Scratch (no allocations anywhere). All counters/flags self-reset per run.
__device__ float    g_part[B * RGRP * S];   // 1 MiB per-(b,rg) column sums
__device__ int      g_idx[B * K];
__device__ int      g_done[B];              // stream-tile completion counters
__device__ int      g_ready[B];             // topk-published flags
__device__ int      g_cd[B];                // gather completion counters
__device__ unsigned g_tick;                 // dynamic work ticket
__device__ int      g_exit;                 // exit counter (resets g_tick)

// ---------------------------------------------------------------------------
// Single fused kernel, DYNAMIC batch-major work queue (fixes R9's convoy:
// blocks that do topk/gather just draw fewer tickets; streaming never stalls).
// Work order: per period v: 256 stream tiles of batch v, then 32 gather
// chunks of batch v-2 (drawn just as ready[v-2] is raised -> ~zero spin).
// Election: 256th completed tile of batch b runs the L2-hot reduce + top-16
// (tie-break smaller index, descending-value emission = lax.top_k semantics).
// Deterministic: fixed summation orders; ticket->work map is fixed.
// ---------------------------------------------------------------------------
__global__ __launch_bounds__(256, 8) void fused_kernel(const float* __restrict__ w,
                                                       const float* __restrict__ x,
                                                       float* __restrict__ out) {
    const int t  = threadIdx.x;
    const int q  = t & 7;                   // float4 col within 32-col tile
    const int rr = t >> 3;                  // row phase 0..31

    __shared__ float s_red[32][33];
    __shared__ float vals[S];               // 8 KB (top-k scratch)
    __shared__ float wv[8];
    __shared__ int   wi[8];
    __shared__ int   s_tmp;
    __shared__ int   s_sidx[K];

    for (;;) {
        if (t == 0) s_tmp = (int)atomicAdd(&g_tick, 1u);
        __syncthreads();
        const unsigned W = (unsigned)s_tmp;
        if (W >= TOTAL_W) break;

        int kind, b, u, gb, ch;             // kind: 0=stream 1=gather 2=nop
        if (W >= (unsigned)(B * PERIOD)) {
            int z = W - B * PERIOD;         // 0..63: appended gathers b=30,31
            kind = 1; gb = B - 2 + (z >> 5); ch = z & (GC - 1);
        } else {
            int v = W / PERIOD, r = W % PERIOD;
            if (r < TILES_PER_B)      { kind = 0; b = v; u = r; }
            else if (v >= 2)          { kind = 1; gb = v - 2; ch = r - TILES_PER_B; }
            else                      { kind = 2; }
        }

        if (kind == 0) {
            // ---- stream a 512x32 tile of w[b] (evict-first; read-once) ----
            const int rg = u >> 6, cc = u & (CGRP - 1);
            const float4* __restrict__ base4 = reinterpret_cast<const float4*>(
                w + ((size_t)b * S + (size_t)rg * TILE_ROWS) * S + cc * TILE_COLS);
            float4 a = make_float4(0.f, 0.f, 0.f, 0.f);
            #pragma unroll 8
            for (int i = 0; i < TILE_ROWS / 32; ++i) {
                float4 v4 = __ldcs(&base4[(size_t)(rr + 32 * i) * (S / 4) + q]);
                a.x += v4.x; a.y += v4.y; a.z += v4.z; a.w += v4.w;
            }
            __syncthreads();                            // s_red reuse guard
            s_red[q * 4 + 0][rr] = a.x;
            s_red[q * 4 + 1][rr] = a.y;
            s_red[q * 4 + 2][rr] = a.z;
            s_red[q * 4 + 3][rr] = a.w;
            __syncthreads();
            if (t < 32) {
                float sum = 0.f;
                #pragma unroll
                for (int j = 0; j < 32; ++j) sum += s_red[t][j];
                g_part[((size_t)b * RGRP + rg) * S + cc * TILE_COLS + t] = sum;
            }
            __syncthreads();
            if (t == 0) {
                __threadfence();                        // publish partial
                s_tmp = atomicAdd(&g_done[b], 1);
            }
            __syncthreads();

            if (s_tmp == TILES_PER_B - 1) {
                // ---- elected: all partials complete; reduce + top-16 ----
                __threadfence();                        // acquire partials
                for (int s = t; s < S; s += 256) {
                    float acc = 0.f;
                    #pragma unroll
                    for (int g = 0; g < RGRP; ++g)
                        acc += g_part[((size_t)b * RGRP + g) * S + s];
                    vals[s] = acc;
                }
                __syncthreads();

                const int lane = t & 31, warp = t >> 5;
                for (int k = 0; k < K; ++k) {
                    float best = -CUDART_INF_F;
                    int bi = S;
                    #pragma unroll
                    for (int j = 0; j < S / 256; ++j) {
                        int s = t + j * 256;
                        float v = vals[s];
                        if (v > best || (v == best && s < bi)) { best = v; bi = s; }
                    }
                    #pragma unroll
                    for (int off = 16; off > 0; off >>= 1) {
                        float ov = __shfl_xor_sync(0xFFFFFFFFu, best, off);
                        int   oi = __shfl_xor_sync(0xFFFFFFFFu, bi,   off);
                        if (ov > best || (ov == best && oi < bi)) { best = ov; bi = oi; }
                    }
                    if (lane == 0) { wv[warp] = best; wi[warp] = bi; }
                    __syncthreads();
                    if (t == 0) {
                        float bb = wv[0]; int ii = wi[0];
                        #pragma unroll
                        for (int wdx = 1; wdx < 8; ++wdx) {
                            if (wv[wdx] > bb || (wv[wdx] == bb && wi[wdx] < ii)) {
                                bb = wv[wdx]; ii = wi[wdx];
                            }
                        }
                        g_idx[b * K + k] = ii;
                        vals[ii] = -CUDART_INF_F;       // knockout
                    }
                    __syncthreads();
                }
                if (t == 0) {
                    g_done[b] = 0;                      // replay reset
                    __threadfence();                    // publish g_idx
                    atomicExch(&g_ready[b], 1);
                }
            }
        } else if (kind == 1) {
            // ---- gather chunk: 32 f-rows x 16 k of out[gb] ----
            if (t == 0) {
                while (((volatile int*)g_ready)[gb] == 0) __nanosleep(64);
            }
            __syncthreads();
            __threadfence();                            // acquire g_idx
            if (t < K) s_sidx[t] = g_idx[gb * K + t];
            __syncthreads();

            const int k  = t & 15;
            const int f0 = ch * 32 + (t >> 4);          // 16 rows per pass
            const int sc = s_sidx[k];
            #pragma unroll
            for (int j = 0; j < 2; ++j) {
                int f = f0 + 16 * j;
                out[((size_t)gb * F + f) * K + k] =
                    __ldg(&x[((size_t)gb * F + f) * S + sc]);
            }
            __syncthreads();
            if (t == 0) {
                int o2 = atomicAdd(&g_cd[gb], 1);
                if (o2 == GC - 1) { g_ready[gb] = 0; g_cd[gb] = 0; }  // reset
            }
        }
        // kind == 2: no-op filler ticket
    }

    // ---- exit: last block out resets the ticket for graph replay ----
    if (t == 0) {
        int e = atomicAdd(&g_exit, 1);
        if (e == NBLK - 1) { g_tick = 0u; g_exit = 0; }
    }
}

extern "C" void kernel_launch(void* const* d_in, const int* in_sizes, int n_in,
                              void* d_out, int out_size) {
    const float* x = (const float*)d_in[0];   // [B, F, S]
    const float* w = (const float*)d_in[1];   // [B, S, S]
    float* out = (float*)d_out;               // [B, F, K]

    fused_kernel<<<NBLK, 256>>>(w, x, out);
}

// round 14
// speedup vs baseline: 5.1371x; 1.2182x over previous
#include <cuda_runtime.h>
#include <math_constants.h>

// Problem constants (from reference setup_inputs)
constexpr int B = 32;
constexpr int F = 1024;
constexpr int S = 2048;
constexpr int K = 16;

constexpr int NBLK = 1024;                  // co-resident: 8/SM * 148 = 1184
constexpr int ROUNDS = 8;                   // 8192 tiles / 1024 blocks
constexpr int TILE_ROWS = 512;
constexpr int TILE_COLS = 32;
constexpr int RGRP = S / TILE_ROWS;         // 4
constexpr int CGRP = S / TILE_COLS;         // 64
constexpr int TILES_PER_B = RGRP * CGRP;    // 256
constexpr int GC = 32;                      // gather chunks per batch (32 f-rows)

// Scratch (no allocations anywhere). All counters/flags self-reset per run.
__device__ float g_part[B * RGRP * S];      // 1 MiB per-(b,rg) column sums
__device__ int   g_idx[B * K];
__device__ int   g_done[B];                 // tile-arrival counters (reset by topk)
__device__ int   g_ready[B];                // topk flags (reset by last gather)
__device__ int   g_cd[B];                   // gather counters (self-reset)

// ---------------------------------------------------------------------------
// Fully static schedule — NO global work queue (R11's single-address ticket
// serialized at ~27cyc/RMW = the whole 135us). Tiles are batch-major:
// round r streams tiles r*1024+j, so 4 batches complete per round (stagger).
// Duties (top-k, gathers) are statically bound to block IDs, executed one
// round AFTER the target batch's tiles complete -> polls are ~instant
// volatile reads. <=2 duties per block over the run -> no convoy feedback.
// Deterministic: fixed summation orders, static work->result mapping.
// Tie-break: smaller index wins; indices emitted in descending-value order
// (matches lax.top_k; gather output ordering depends on it).
// ---------------------------------------------------------------------------
__global__ __launch_bounds__(256, 8) void fused_kernel(const float* __restrict__ w,
                                                       const float* __restrict__ x,
                                                       float* __restrict__ out) {
    const int j  = blockIdx.x;
    const int t  = threadIdx.x;
    const int q  = t & 7;                   // float4 col within 32-col tile
    const int rr = t >> 3;                  // row phase 0..31

    __shared__ float s_red[32][33];
    __shared__ float vals[S];               // 8 KB top-k scratch
    __shared__ float wv[8];
    __shared__ int   wi[8];
    __shared__ int   s_sidx[K];

    for (int r = 0; r <= ROUNDS; ++r) {
        // ================= stream this round's tile =================
        if (r < ROUNDS) {
            const int T  = r * NBLK + j;           // batch-major tile id
            const int b  = T >> 8;                 // / TILES_PER_B
            const int u  = T & (TILES_PER_B - 1);
            const int rg = u >> 6, cc = u & (CGRP - 1);

            const float4* __restrict__ base4 = reinterpret_cast<const float4*>(
                w + ((size_t)b * S + (size_t)rg * TILE_ROWS) * S + cc * TILE_COLS);
            float4 a = make_float4(0.f, 0.f, 0.f, 0.f);
            #pragma unroll
            for (int i = 0; i < TILE_ROWS / 32; ++i) {     // 16 LDG.128, deep MLP
                float4 v = __ldcs(&base4[(size_t)(rr + 32 * i) * (S / 4) + q]);
                a.x += v.x; a.y += v.y; a.z += v.z; a.w += v.w;
            }
            __syncthreads();                               // s_red reuse guard
            s_red[q * 4 + 0][rr] = a.x;
            s_red[q * 4 + 1][rr] = a.y;
            s_red[q * 4 + 2][rr] = a.z;
            s_red[q * 4 + 3][rr] = a.w;
            __syncthreads();
            if (t < 32) {
                float sum = 0.f;
                #pragma unroll
                for (int jj = 0; jj < 32; ++jj) sum += s_red[t][jj];
                g_part[((size_t)b * RGRP + rg) * S + cc * TILE_COLS + t] = sum;
            }
            __syncthreads();                               // publish within block
            if (t == 0) {
                __threadfence();                           // publish device-wide
                atomicAdd(&g_done[b], 1);                  // 32 addrs, spread out
            }
        }

        // ============ duties for batches finished last round ============
        if (r >= 1) {
            #pragma unroll
            for (int b4 = 0; b4 < 4; ++b4) {
                const int b = (r - 1) * 4 + b4;
                const int i = (j - b * 33) & (NBLK - 1);   // true mod (pow2)
                if (i > GC) continue;                      // not my duty

                if (i == GC) {
                    // ---- top-k duty: poll tiles done, reduce, top-16 ----
                    if (t == 0) {
                        while (((volatile int*)g_done)[b] != TILES_PER_B)
                            __nanosleep(64);
                    }
                    __syncthreads();
                    __threadfence();                       // acquire partials
                    for (int s = t; s < S; s += 256) {
                        float acc = 0.f;
                        #pragma unroll
                        for (int g = 0; g < RGRP; ++g)
                            acc += g_part[((size_t)b * RGRP + g) * S + s];
                        vals[s] = acc;
                    }
                    __syncthreads();

                    const int lane = t & 31, warp = t >> 5;
                    for (int k = 0; k < K; ++k) {
                        float best = -CUDART_INF_F;
                        int bi = S;
                        #pragma unroll
                        for (int jj = 0; jj < S / 256; ++jj) {
                            int s = t + jj * 256;
                            float v = vals[s];
                            if (v > best || (v == best && s < bi)) { best = v; bi = s; }
                        }
                        #pragma unroll
                        for (int off = 16; off > 0; off >>= 1) {
                            float ov = __shfl_xor_sync(0xFFFFFFFFu, best, off);
                            int   oi = __shfl_xor_sync(0xFFFFFFFFu, bi,   off);
                            if (ov > best || (ov == best && oi < bi)) { best = ov; bi = oi; }
                        }
                        if (lane == 0) { wv[warp] = best; wi[warp] = bi; }
                        __syncthreads();
                        if (t == 0) {
                            float bb = wv[0]; int ii = wi[0];
                            #pragma unroll
                            for (int wdx = 1; wdx < 8; ++wdx) {
                                if (wv[wdx] > bb || (wv[wdx] == bb && wi[wdx] < ii)) {
                                    bb = wv[wdx]; ii = wi[wdx];
                                }
                            }
                            g_idx[b * K + k] = ii;
                            vals[ii] = -CUDART_INF_F;      // knockout
                        }
                        __syncthreads();
                    }
                    if (t == 0) {
                        g_done[b] = 0;                     // replay reset (safe: full)
                        __threadfence();                   // publish g_idx
                        atomicExch(&g_ready[b], 1);
                    }
                } else {
                    // ---- gather duty: chunk i = 32 f-rows of out[b] ----
                    if (t == 0) {
                        while (((volatile int*)g_ready)[b] == 0) __nanosleep(64);
                    }
                    __syncthreads();
                    __threadfence();                       // acquire g_idx
                    if (t < K) s_sidx[t] = g_idx[b * K + t];
                    __syncthreads();

                    const int k  = t & 15;
                    const int sc = s_sidx[k];
                    const int f0 = i * 32 + (t >> 4);
                    out[((size_t)b * F + f0) * K + k] =
                        __ldg(&x[((size_t)b * F + f0) * S + sc]);
                    const int f1 = f0 + 16;
                    out[((size_t)b * F + f1) * K + k] =
                        __ldg(&x[((size_t)b * F + f1) * S + sc]);
                    __syncthreads();
                    if (t == 0) {
                        int o2 = atomicAdd(&g_cd[b], 1);
                        if (o2 == GC - 1) { g_ready[b] = 0; g_cd[b] = 0; }  // reset
                    }
                }
            }
        }
    }
}

extern "C" void kernel_launch(void* const* d_in, const int* in_sizes, int n_in,
                              void* d_out, int out_size) {
    const float* x = (const float*)d_in[0];   // [B, F, S]
    const float* w = (const float*)d_in[1];   // [B, S, S]
    float* out = (float*)d_out;               // [B, F, K]

    fused_kernel<<<NBLK, 256>>>(w, x, out);
}

// round 15
// speedup vs baseline: 5.2334x; 1.0187x over previous
#include <cuda_runtime.h>
#include <math_constants.h>

// Problem constants (from reference setup_inputs)
constexpr int B = 32;
constexpr int F = 1024;
constexpr int S = 2048;
constexpr int K = 16;

constexpr int NSTREAM = 1024;               // streamer blocks
constexpr int NSVC = 2 * B;                 // service blocks (2 per batch)
constexpr int NBLK = NSTREAM + NSVC;        // 1088 <= 8/SM*148 = 1184 (co-resident)

constexpr int SLAB_ROWS = 128;
constexpr int SLAB_COLS = 512;
constexpr int RC = S / SLAB_ROWS;           // 16 row-chunks per batch
constexpr int CC = S / SLAB_COLS;           // 4  col-chunks per batch
constexpr int SLABS_PER_B = RC * CC;        // 64
constexpr int PHASES = 2;                   // batch-major: 0-15 then 16-31

// Scratch (no allocations anywhere). Counters/flags self-reset per run.
__device__ float g_part[B * RC * S];        // 4 MiB per-(b,rc) column sums
__device__ int   g_idx[B * K];
__device__ int   g_done[B];                 // slab-arrival counters (reset by topk)
__device__ int   g_ready[B];                // topk flags (reset by gather-half-1)

// ---------------------------------------------------------------------------
// Block-specialized fused kernel.
//   Streamers (j < 1024): two back-to-back 128x512 slabs of w, batch-major
//   (phase 0 = batches 0..15, phase 1 = 16..31). 64 contiguous LDG.128 per
//   thread per slab (deep MLP, evict-first), tiny smem reduce, one atomicAdd.
//   NO polls, NO duties -> stream quality of the 84.6%-DRAM R3 kernel.
//   Service blocks (2 per batch): (b,0) polls g_done[b]==64 (volatile), does
//   L2-hot reduce + iterative top-16 (tie-break smaller index, descending
//   emission = lax.top_k), publishes g_idx/ready, gathers f 0..511.
//   (b,1) polls ready[b], gathers f 512..1023. Phase-0 batches' service work
//   overlaps phase-1 streaming; tail = phase-1 service only (~7us).
//   Deterministic: fixed summation orders, static work->result mapping.
// ---------------------------------------------------------------------------
__global__ __launch_bounds__(256, 8) void fused_kernel(const float* __restrict__ w,
                                                       const float* __restrict__ x,
                                                       float* __restrict__ out) {
    const int t = threadIdx.x;

    __shared__ float4 s_v4[128];            // streamer cross-rowgroup reduce
    __shared__ float  vals[S];              // service top-k scratch (8 KB)
    __shared__ float  wv[8];
    __shared__ int    wi[8];
    __shared__ int    s_sidx[K];

    if (blockIdx.x < NSTREAM) {
        // ======================= STREAMER =======================
        const int j   = blockIdx.x;
        const int rg2 = t >> 7;             // row group 0/1 (64 rows each)
        const int cq  = t & 127;            // float4 column 0..127

        #pragma unroll
        for (int p = 0; p < PHASES; ++p) {
            const int G  = p * NSTREAM + j;         // batch-major slab id
            const int b  = G >> 6;                  // / SLABS_PER_B
            const int u  = G & (SLABS_PER_B - 1);
            const int rc = u >> 2;                  // 0..15
            const int cc = u & (CC - 1);            // 0..3

            const float4* __restrict__ base4 = reinterpret_cast<const float4*>(
                w + ((size_t)b * S + (size_t)rc * SLAB_ROWS) * S + cc * SLAB_COLS);

            float4 a = make_float4(0.f, 0.f, 0.f, 0.f);
            #pragma unroll 8
            for (int i = 0; i < 64; ++i) {          // 64 contiguous LDG.128
                float4 v = __ldcs(&base4[(size_t)(rg2 * 64 + i) * (S / 4) + cq]);
                a.x += v.x; a.y += v.y; a.z += v.z; a.w += v.w;
            }
            __syncthreads();                        // smem reuse guard
            if (rg2 == 1) s_v4[cq] = a;
            __syncthreads();
            if (rg2 == 0) {
                float4 o = s_v4[cq];
                a.x += o.x; a.y += o.y; a.z += o.z; a.w += o.w;
                reinterpret_cast<float4*>(
                    g_part + ((size_t)b * RC + rc) * S + cc * SLAB_COLS)[cq] = a;
            }
            __syncthreads();
            if (t == 0) {
                __threadfence();                    // publish partial
                atomicAdd(&g_done[b], 1);           // 32 addrs, spread over run
            }
        }
        return;
    }

    // ======================= SERVICE =======================
    const int sb = blockIdx.x - NSTREAM;    // 0..63
    const int b  = sb >> 1;
    const int h  = sb & 1;                  // half of the gather

    if (h == 0) {
        // ---- top-k duty ----
        if (t == 0) {
            while (((volatile int*)g_done)[b] != SLABS_PER_B) __nanosleep(128);
        }
        __syncthreads();
        __threadfence();                            // acquire partials

        for (int s = t; s < S; s += 256) {
            float acc = 0.f;
            #pragma unroll
            for (int rc = 0; rc < RC; ++rc)
                acc += g_part[((size_t)b * RC + rc) * S + s];
            vals[s] = acc;
        }
        __syncthreads();

        const int lane = t & 31, warp = t >> 5;
        for (int k = 0; k < K; ++k) {
            float best = -CUDART_INF_F;
            int bi = S;
            #pragma unroll
            for (int jj = 0; jj < S / 256; ++jj) {
                int s = t + jj * 256;
                float v = vals[s];
                if (v > best || (v == best && s < bi)) { best = v; bi = s; }
            }
            #pragma unroll
            for (int off = 16; off > 0; off >>= 1) {
                float ov = __shfl_xor_sync(0xFFFFFFFFu, best, off);
                int   oi = __shfl_xor_sync(0xFFFFFFFFu, bi,   off);
                if (ov > best || (ov == best && oi < bi)) { best = ov; bi = oi; }
            }
            if (lane == 0) { wv[warp] = best; wi[warp] = bi; }
            __syncthreads();
            if (t == 0) {
                float bb = wv[0]; int ii = wi[0];
                #pragma unroll
                for (int wdx = 1; wdx < 8; ++wdx) {
                    if (wv[wdx] > bb || (wv[wdx] == bb && wi[wdx] < ii)) {
                        bb = wv[wdx]; ii = wi[wdx];
                    }
                }
                g_idx[b * K + k] = ii;
                vals[ii] = -CUDART_INF_F;           // knockout
            }
            __syncthreads();
        }
        if (t == 0) {
            g_done[b] = 0;                          // replay reset (count full)
            __threadfence();                        // publish g_idx
            atomicExch(&g_ready[b], 1);
        }
        __syncthreads();
    } else {
        // ---- wait for indices ----
        if (t == 0) {
            while (((volatile int*)g_ready)[b] == 0) __nanosleep(128);
        }
        __syncthreads();
        __threadfence();                            // acquire g_idx
    }

    // ---- gather my half of out[b]: f in [h*512, h*512+512) ----
    if (t < K) s_sidx[t] = g_idx[b * K + t];
    __syncthreads();

    const int k  = t & 15;
    const int sc = s_sidx[k];
    const int fb = h * (F / 2) + (t >> 4);          // 16 f-rows per pass
    #pragma unroll 4
    for (int pass = 0; pass < (F / 2) / 16; ++pass) {   // 32 passes
        int f = fb + 16 * pass;
        out[((size_t)b * F + f) * K + k] =
            __ldg(&x[((size_t)b * F + f) * S + sc]);
    }

    if (h == 1) {
        __syncthreads();
        if (t == 0) g_ready[b] = 0;                 // replay reset (last consumer)
    }
}

extern "C" void kernel_launch(void* const* d_in, const int* in_sizes, int n_in,
                              void* d_out, int out_size) {
    const float* x = (const float*)d_in[0];   // [B, F, S]
    const float* w = (const float*)d_in[1];   // [B, S, S]
    float* out = (float*)d_out;               // [B, F, K]

    fused_kernel<<<NBLK, 256>>>(w, x, out);
}